// round 6
// baseline (speedup 1.0000x reference)
#include <cuda_runtime.h>
#include <cstdint>

#define BATCH 4
#define SEQ   2048
#define DIM   768
#define NHEAD 12
#define HDIM  64
#define QKVC  (3*DIM)            // 2304
#define ROWS  (BATCH*SEQ)        // 8192
#define ATT_SCALE 0.125f
#define LOG2E 1.44269504088896340736f

// Scratch (allocation-free rule: __device__ globals)
__device__ float g_qkv[(size_t)ROWS * QKVC];   // [B*N, 3*H*D]
__device__ float g_att[(size_t)ROWS * DIM];    // [B*N, H*D]
__device__ float g_Wt1[(size_t)QKVC * DIM];    // Wqkv^T  [2304, 768] (K-major)
__device__ float g_Wt2[(size_t)DIM * DIM];     // Wproj^T [768, 768]

// ---------------------------------------------------------------------------
// helpers (non-'a' features only: supported on plain sm_103 target)
// ---------------------------------------------------------------------------
__device__ __forceinline__ uint32_t f2tf32(float f) {
    uint32_t r;
    asm("cvt.rna.tf32.f32 %0, %1;" : "=r"(r) : "f"(f));
    return r;
}
__device__ __forceinline__ float ex2(float x) {
    float r;
    asm("ex2.approx.ftz.f32 %0, %1;" : "=f"(r) : "f"(x));
    return r;
}
__device__ __forceinline__ uint32_t smem_u32(const void* p) {
    uint32_t a;
    asm("{ .reg .u64 t; cvta.to.shared.u64 t, %1; cvt.u32.u64 %0, t; }"
        : "=r"(a) : "l"(p));
    return a;
}
__device__ __forceinline__ void cp_async16(uint32_t saddr, const void* gptr) {
    asm volatile("cp.async.cg.shared.global [%0], [%1], 16;"
                 :: "r"(saddr), "l"(gptr) : "memory");
}
#define CP_COMMIT() asm volatile("cp.async.commit_group;" ::: "memory")
#define CP_WAIT(n)  asm volatile("cp.async.wait_group %0;" :: "n"(n) : "memory")

// D += A(16x8) * B(8x8), tf32 inputs, fp32 accum
__device__ __forceinline__ void mma16n8k8(float c[4], const uint32_t a[4],
                                          const uint32_t b[2]) {
    asm volatile(
        "mma.sync.aligned.m16n8k8.row.col.f32.tf32.tf32.f32 "
        "{%0,%1,%2,%3}, {%4,%5,%6,%7}, {%8,%9}, {%0,%1,%2,%3};"
        : "+f"(c[0]), "+f"(c[1]), "+f"(c[2]), "+f"(c[3])
        : "r"(a[0]), "r"(a[1]), "r"(a[2]), "r"(a[3]), "r"(b[0]), "r"(b[1]));
}

// ---------------------------------------------------------------------------
// Transpose: dst[c*R + r] = src[r*C + c]   (src: [R, C])
// ---------------------------------------------------------------------------
__global__ void transpose_k(const float* __restrict__ src, float* __restrict__ dst,
                            int R, int C)
{
    __shared__ float t[32][33];
    int bx = blockIdx.x * 32;
    int by = blockIdx.y * 32;
    #pragma unroll
    for (int i = 0; i < 32; i += 8)
        t[threadIdx.y + i][threadIdx.x] =
            src[(size_t)(by + threadIdx.y + i) * C + bx + threadIdx.x];
    __syncthreads();
    #pragma unroll
    for (int i = 0; i < 32; i += 8)
        dst[(size_t)(bx + threadIdx.y + i) * R + by + threadIdx.x] =
            t[threadIdx.x][threadIdx.y + i];
}

// ---------------------------------------------------------------------------
// tf32 mma.sync GEMM, v2: KC=16, stride 20 -> 40KB smem -> 2 CTAs/SM.
// 128x128 CTA tile, 8 warps (2x4), 64x32 per warp.
// ---------------------------------------------------------------------------
#define KC 16
#define SSTRIDE 20
#define TILE_F (128 * SSTRIDE)

extern __shared__ float g_smem[];

__global__ __launch_bounds__(256, 2) void gemm_mma(
    const float* __restrict__ A, const float* __restrict__ Bt,
    const float* __restrict__ bias, float* __restrict__ C,
    int Ncols, int K, int addBias)
{
    float* As[2] = { g_smem,              g_smem + 2 * TILE_F };
    float* Bs[2] = { g_smem + TILE_F,     g_smem + 3 * TILE_F };

    const int tid  = threadIdx.x;
    const int lane = tid & 31;
    const int wid  = tid >> 5;
    const int gid  = lane >> 2;
    const int tig  = lane & 3;
    const int wr   = wid >> 2;
    const int wc   = wid & 3;
    const int bm = blockIdx.y * 128, bn = blockIdx.x * 128;

    const float* Ag = A  + (size_t)bm * K;
    const float* Bg = Bt + (size_t)bn * K;

    float acc[4][4][4];
    #pragma unroll
    for (int mt = 0; mt < 4; mt++)
        #pragma unroll
        for (int nt = 0; nt < 4; nt++)
            #pragma unroll
            for (int i = 0; i < 4; i++) acc[mt][nt][i] = 0.f;

    float4 pa[2], pb[2];
    const int nch = K / KC;   // 48

    // ---- prefetch chunk 0 : tile = 128 rows x 16 floats = 512 float4 ----
    #pragma unroll
    for (int i = 0; i < 2; i++) {
        int slot = tid + i * 256;       // 0..511
        int row  = slot >> 2;
        int q    = slot & 3;
        pa[i] = *(const float4*)(Ag + (size_t)row * K + q * 4);
        pb[i] = *(const float4*)(Bg + (size_t)row * K + q * 4);
    }
    #pragma unroll
    for (int i = 0; i < 2; i++) {
        int slot = tid + i * 256;
        int row  = slot >> 2;
        int q    = slot & 3;
        float* pA = As[0] + row * SSTRIDE + q * 4;
        float* pB = Bs[0] + row * SSTRIDE + q * 4;
        pA[0] = __uint_as_float(f2tf32(pa[i].x));
        pA[1] = __uint_as_float(f2tf32(pa[i].y));
        pA[2] = __uint_as_float(f2tf32(pa[i].z));
        pA[3] = __uint_as_float(f2tf32(pa[i].w));
        pB[0] = __uint_as_float(f2tf32(pb[i].x));
        pB[1] = __uint_as_float(f2tf32(pb[i].y));
        pB[2] = __uint_as_float(f2tf32(pb[i].z));
        pB[3] = __uint_as_float(f2tf32(pb[i].w));
    }
    __syncthreads();

    for (int c = 0; c < nch; c++) {
        const int buf = c & 1;
        if (c + 1 < nch) {
            const float* Agn = Ag + (c + 1) * KC;
            const float* Bgn = Bg + (c + 1) * KC;
            #pragma unroll
            for (int i = 0; i < 2; i++) {
                int slot = tid + i * 256;
                int row  = slot >> 2;
                int q    = slot & 3;
                pa[i] = *(const float4*)(Agn + (size_t)row * K + q * 4);
                pb[i] = *(const float4*)(Bgn + (size_t)row * K + q * 4);
            }
        }

        const uint32_t* Au = (const uint32_t*)As[buf];
        const uint32_t* Bu = (const uint32_t*)Bs[buf];
        #pragma unroll
        for (int ks = 0; ks < 2; ks++) {
            const int k0 = ks * 8;
            uint32_t af[4][4], bf[4][2];
            #pragma unroll
            for (int mt = 0; mt < 4; mt++) {
                int rb = wr * 64 + mt * 16;
                af[mt][0] = Au[(rb + gid)     * SSTRIDE + k0 + tig];
                af[mt][1] = Au[(rb + gid + 8) * SSTRIDE + k0 + tig];
                af[mt][2] = Au[(rb + gid)     * SSTRIDE + k0 + tig + 4];
                af[mt][3] = Au[(rb + gid + 8) * SSTRIDE + k0 + tig + 4];
            }
            #pragma unroll
            for (int nt = 0; nt < 4; nt++) {
                int cb = wc * 32 + nt * 8 + gid;
                bf[nt][0] = Bu[cb * SSTRIDE + k0 + tig];
                bf[nt][1] = Bu[cb * SSTRIDE + k0 + tig + 4];
            }
            #pragma unroll
            for (int mt = 0; mt < 4; mt++)
                #pragma unroll
                for (int nt = 0; nt < 4; nt++)
                    mma16n8k8(acc[mt][nt], af[mt], bf[nt]);
        }

        if (c + 1 < nch) {
            const int nb = (c + 1) & 1;
            #pragma unroll
            for (int i = 0; i < 2; i++) {
                int slot = tid + i * 256;
                int row  = slot >> 2;
                int q    = slot & 3;
                float* pA = As[nb] + row * SSTRIDE + q * 4;
                float* pB = Bs[nb] + row * SSTRIDE + q * 4;
                pA[0] = __uint_as_float(f2tf32(pa[i].x));
                pA[1] = __uint_as_float(f2tf32(pa[i].y));
                pA[2] = __uint_as_float(f2tf32(pa[i].z));
                pA[3] = __uint_as_float(f2tf32(pa[i].w));
                pB[0] = __uint_as_float(f2tf32(pb[i].x));
                pB[1] = __uint_as_float(f2tf32(pb[i].y));
                pB[2] = __uint_as_float(f2tf32(pb[i].z));
                pB[3] = __uint_as_float(f2tf32(pb[i].w));
            }
        }
        __syncthreads();
    }

    #pragma unroll
    for (int mt = 0; mt < 4; mt++) {
        int r0 = bm + wr * 64 + mt * 16 + gid;
        #pragma unroll
        for (int nt = 0; nt < 4; nt++) {
            int cc = bn + wc * 32 + nt * 8 + tig * 2;
            float b0 = 0.f, b1 = 0.f;
            if (addBias) { b0 = bias[cc]; b1 = bias[cc + 1]; }
            float2 v0 = { acc[mt][nt][0] + b0, acc[mt][nt][1] + b1 };
            float2 v1 = { acc[mt][nt][2] + b0, acc[mt][nt][3] + b1 };
            *(float2*)(C + (size_t)r0 * Ncols + cc)       = v0;
            *(float2*)(C + (size_t)(r0 + 8) * Ncols + cc) = v1;
        }
    }
}

// ---------------------------------------------------------------------------
// Tensor-core flash attention, v3:
//  - cp.async double-buffered K/V (raw fp32)
//  - cooperative ONE-PASS in-place tf32 conversion per tile (vectorized)
//  - fragment loads are raw uint32 (no per-warp redundant cvt)
//  - 2 CTAs/SM, exp2-domain softmax
// Smem: KV[2][128][72] + Ss[128][72] floats = 110592 B.
// ---------------------------------------------------------------------------
#define AST 72
#define KT  64
#define NTILES (SEQ / KT)

__global__ __launch_bounds__(256, 2) void attn_mma()
{
    float* KV[2] = { g_smem, g_smem + 128 * AST };      // K rows 0..63, V rows 64..127
    float* Ss    = g_smem + 2 * 128 * AST;              // [128][72]

    const int tid  = threadIdx.x;
    const int lane = tid & 31;
    const int wid  = tid >> 5;          // 0..7
    const int gid  = lane >> 2;         // 0..7
    const int tig  = lane & 3;          // 0..3
    const int wb   = wid * 16;

    const int bh = blockIdx.y;
    const int b  = bh / NHEAD;
    const int h  = bh - b * NHEAD;
    const int qbase = blockIdx.x * 128;

    const float* kbase = g_qkv + (size_t)(b * SEQ) * QKVC + DIM + h * HDIM;
    const float* vbase = kbase + DIM;

    // staging addresses (this thread's 4 slots)
    const int srow = tid >> 4;           // 0..15
    const int sq   = tid & 15;
    uint32_t kv_s[2][2];
    #pragma unroll
    for (int bu = 0; bu < 2; bu++) {
        kv_s[bu][0] = smem_u32(KV[bu] + srow * AST + sq * 4);
        kv_s[bu][1] = smem_u32(KV[bu] + (64 + srow) * AST + sq * 4);
    }

    // ---- Q fragments (A operand), scaled by ATT_SCALE*log2e, tf32 ----
    uint32_t qf[8][4];
    {
        const float qs = ATT_SCALE * LOG2E;
        const float* Qg = g_qkv + (size_t)(b * SEQ + qbase + wb) * QKVC + h * HDIM;
        #pragma unroll
        for (int ks = 0; ks < 8; ks++) {
            int k0 = ks * 8;
            qf[ks][0] = f2tf32(Qg[(size_t)gid       * QKVC + k0 + tig]     * qs);
            qf[ks][1] = f2tf32(Qg[(size_t)(gid + 8) * QKVC + k0 + tig]     * qs);
            qf[ks][2] = f2tf32(Qg[(size_t)gid       * QKVC + k0 + tig + 4] * qs);
            qf[ks][3] = f2tf32(Qg[(size_t)(gid + 8) * QKVC + k0 + tig + 4] * qs);
        }
    }

    float of[8][4];
    #pragma unroll
    for (int nt = 0; nt < 8; nt++)
        #pragma unroll
        for (int i = 0; i < 4; i++) of[nt][i] = 0.f;
    float m0 = -1e30f, m1 = -1e30f, l0 = 0.f, l1 = 0.f;

    // ---- stage tile 0 ----
    #pragma unroll
    for (int i = 0; i < 4; i++) {
        int row = srow + i * 16;
        cp_async16(kv_s[0][0] + i * 16 * AST * 4,
                   kbase + (size_t)row * QKVC + sq * 4);
        cp_async16(kv_s[0][1] + i * 16 * AST * 4,
                   vbase + (size_t)row * QKVC + sq * 4);
    }
    CP_COMMIT();

    for (int t = 0; t < NTILES; t++) {
        const int buf = t & 1;
        if (t + 1 < NTILES) {
            const int nb = buf ^ 1;
            const int kt = (t + 1) * KT;
            #pragma unroll
            for (int i = 0; i < 4; i++) {
                int row = srow + i * 16;
                cp_async16(kv_s[nb][0] + i * 16 * AST * 4,
                           kbase + (size_t)(kt + row) * QKVC + sq * 4);
                cp_async16(kv_s[nb][1] + i * 16 * AST * 4,
                           vbase + (size_t)(kt + row) * QKVC + sq * 4);
            }
            CP_COMMIT();
            CP_WAIT(1);
        } else {
            CP_WAIT(0);
        }
        __syncthreads();

        // ---- cooperative in-place tf32 conversion of K+V tile ----
        // 128 rows x 16 float4 = 2048 slots / 256 threads = 8 per thread
        #pragma unroll
        for (int i = 0; i < 8; i++) {
            int idx = tid + i * 256;
            int row = idx >> 4;
            int q   = idx & 15;
            float4* p = (float4*)(KV[buf] + row * AST + q * 4);
            float4 v = *p;
            v.x = __uint_as_float(f2tf32(v.x));
            v.y = __uint_as_float(f2tf32(v.y));
            v.z = __uint_as_float(f2tf32(v.z));
            v.w = __uint_as_float(f2tf32(v.w));
            *p = v;
        }
        __syncthreads();

        const uint32_t* Ku = (const uint32_t*)KV[buf];
        const uint32_t* Vu = (const uint32_t*)(KV[buf] + 64 * AST);

        // ---- S = Q @ K^T ----
        float sc[8][4];
        #pragma unroll
        for (int nt = 0; nt < 8; nt++)
            #pragma unroll
            for (int i = 0; i < 4; i++) sc[nt][i] = 0.f;

        #pragma unroll
        for (int ks = 0; ks < 8; ks++) {
            const int k0 = ks * 8;
            #pragma unroll
            for (int nt = 0; nt < 8; nt++) {
                uint32_t bf[2];
                bf[0] = Ku[(nt * 8 + gid) * AST + k0 + tig];
                bf[1] = Ku[(nt * 8 + gid) * AST + k0 + tig + 4];
                mma16n8k8(sc[nt], qf[ks], bf);
            }
        }

        // ---- online softmax (log2 domain, quad shfl reductions) ----
        float tm0 = -1e30f, tm1 = -1e30f;
        #pragma unroll
        for (int nt = 0; nt < 8; nt++) {
            tm0 = fmaxf(tm0, fmaxf(sc[nt][0], sc[nt][1]));
            tm1 = fmaxf(tm1, fmaxf(sc[nt][2], sc[nt][3]));
        }
        tm0 = fmaxf(tm0, __shfl_xor_sync(0xffffffffu, tm0, 1));
        tm0 = fmaxf(tm0, __shfl_xor_sync(0xffffffffu, tm0, 2));
        tm1 = fmaxf(tm1, __shfl_xor_sync(0xffffffffu, tm1, 1));
        tm1 = fmaxf(tm1, __shfl_xor_sync(0xffffffffu, tm1, 2));

        float m0n = fmaxf(m0, tm0);
        float m1n = fmaxf(m1, tm1);
        float c0 = ex2(m0 - m0n);
        float c1 = ex2(m1 - m1n);

        float s0 = 0.f, s1 = 0.f;
        #pragma unroll
        for (int nt = 0; nt < 8; nt++) {
            sc[nt][0] = ex2(sc[nt][0] - m0n);
            sc[nt][1] = ex2(sc[nt][1] - m0n);
            sc[nt][2] = ex2(sc[nt][2] - m1n);
            sc[nt][3] = ex2(sc[nt][3] - m1n);
            s0 += sc[nt][0] + sc[nt][1];
            s1 += sc[nt][2] + sc[nt][3];
        }
        s0 += __shfl_xor_sync(0xffffffffu, s0, 1);
        s0 += __shfl_xor_sync(0xffffffffu, s0, 2);
        s1 += __shfl_xor_sync(0xffffffffu, s1, 1);
        s1 += __shfl_xor_sync(0xffffffffu, s1, 2);

        l0 = l0 * c0 + s0;
        l1 = l1 * c1 + s1;
        m0 = m0n; m1 = m1n;

        #pragma unroll
        for (int nt = 0; nt < 8; nt++) {
            of[nt][0] *= c0; of[nt][1] *= c0;
            of[nt][2] *= c1; of[nt][3] *= c1;
        }

        // ---- stage P (tf32) via smem (warp-private rows) ----
        #pragma unroll
        for (int nt = 0; nt < 8; nt++) {
            float2 p0 = { __uint_as_float(f2tf32(sc[nt][0])),
                          __uint_as_float(f2tf32(sc[nt][1])) };
            float2 p1 = { __uint_as_float(f2tf32(sc[nt][2])),
                          __uint_as_float(f2tf32(sc[nt][3])) };
            *(float2*)(Ss + (wb + gid)     * AST + nt * 8 + tig * 2) = p0;
            *(float2*)(Ss + (wb + gid + 8) * AST + nt * 8 + tig * 2) = p1;
        }
        __syncwarp();

        // ---- O += P @ V ----
        const uint32_t* Pu = (const uint32_t*)Ss;
        #pragma unroll
        for (int ks = 0; ks < 8; ks++) {
            const int k0 = ks * 8;
            uint32_t af[4];
            af[0] = Pu[(wb + gid)     * AST + k0 + tig];
            af[1] = Pu[(wb + gid + 8) * AST + k0 + tig];
            af[2] = Pu[(wb + gid)     * AST + k0 + tig + 4];
            af[3] = Pu[(wb + gid + 8) * AST + k0 + tig + 4];
            #pragma unroll
            for (int nt = 0; nt < 8; nt++) {
                uint32_t bf[2];
                bf[0] = Vu[(k0 + tig)     * AST + nt * 8 + gid];
                bf[1] = Vu[(k0 + tig + 4) * AST + nt * 8 + gid];
                mma16n8k8(of[nt], af, bf);
            }
        }
        __syncthreads();   // all warps done with buf before it is restaged
    }

    // ---- epilogue ----
    const float inv0 = 1.f / l0;
    const float inv1 = 1.f / l1;
    const int r0 = b * SEQ + qbase + wb + gid;
    #pragma unroll
    for (int nt = 0; nt < 8; nt++) {
        int col = h * HDIM + nt * 8 + tig * 2;
        float2 v0 = { of[nt][0] * inv0, of[nt][1] * inv0 };
        float2 v1 = { of[nt][2] * inv1, of[nt][3] * inv1 };
        *(float2*)(g_att + (size_t)r0 * DIM + col)       = v0;
        *(float2*)(g_att + (size_t)(r0 + 8) * DIM + col) = v1;
    }
}

// ---------------------------------------------------------------------------
extern "C" void kernel_launch(void* const* d_in, const int* in_sizes, int n_in,
                              void* d_out, int out_size)
{
    const float* x     = (const float*)d_in[0];   // [4,2048,768]
    const float* Wqkv  = (const float*)d_in[1];   // [768,2304]
    const float* Wproj = (const float*)d_in[2];   // [768,768]
    const float* bproj = (const float*)d_in[3];   // [768]
    float* out = (float*)d_out;

    float *qkv_ptr, *att_ptr, *wt1_ptr, *wt2_ptr;
    cudaGetSymbolAddress((void**)&qkv_ptr, g_qkv);
    cudaGetSymbolAddress((void**)&att_ptr, g_att);
    cudaGetSymbolAddress((void**)&wt1_ptr, g_Wt1);
    cudaGetSymbolAddress((void**)&wt2_ptr, g_Wt2);

    const int smem_gemm = 4 * TILE_F * sizeof(float);              // 40960
    const int smem_attn = (2 * 128 + 128) * AST * sizeof(float);   // 110592
    cudaFuncSetAttribute(gemm_mma, cudaFuncAttributeMaxDynamicSharedMemorySize,
                         smem_gemm);
    cudaFuncSetAttribute(attn_mma, cudaFuncAttributeMaxDynamicSharedMemorySize,
                         smem_attn);

    // 0) transpose weights to K-major
    transpose_k<<<dim3(QKVC / 32, DIM / 32), dim3(32, 8)>>>(Wqkv, wt1_ptr, DIM, QKVC);
    transpose_k<<<dim3(DIM / 32, DIM / 32), dim3(32, 8)>>>(Wproj, wt2_ptr, DIM, DIM);

    // 1) qkv = x @ Wqkv            (tf32 mma.sync)
    gemm_mma<<<dim3(QKVC / 128, ROWS / 128), 256, smem_gemm>>>(
        x, wt1_ptr, nullptr, qkv_ptr, QKVC, DIM, 0);

    // 2) attention (tensor-core flash, pipelined)
    attn_mma<<<dim3(SEQ / 128, BATCH * NHEAD), 256, smem_attn>>>();

    // 3) out = att @ Wproj + bproj (tf32 mma.sync)
    gemm_mma<<<dim3(DIM / 128, ROWS / 128), 256, smem_gemm>>>(
        att_ptr, wt2_ptr, bproj, out, DIM, DIM, 1);
}

// round 7
// speedup vs baseline: 1.0695x; 1.0695x over previous
#include <cuda_runtime.h>
#include <cstdint>

#define BATCH 4
#define SEQ   2048
#define DIM   768
#define NHEAD 12
#define HDIM  64
#define QKVC  (3*DIM)            // 2304
#define ROWS  (BATCH*SEQ)        // 8192
#define ATT_SCALE 0.125f
#define LOG2E 1.44269504088896340736f

// Scratch (allocation-free rule: __device__ globals)
__device__ float g_qkv[(size_t)ROWS * QKVC];   // [B*N, 3*H*D] (tf32-rounded)
__device__ float g_att[(size_t)ROWS * DIM];    // [B*N, H*D]
__device__ float g_Wt1[(size_t)QKVC * DIM];    // Wqkv^T  [2304, 768] (K-major)
__device__ float g_Wt2[(size_t)DIM * DIM];     // Wproj^T [768, 768]

// ---------------------------------------------------------------------------
// helpers (non-'a' features only: supported on plain sm_103 target)
// ---------------------------------------------------------------------------
__device__ __forceinline__ uint32_t f2tf32(float f) {
    uint32_t r;
    asm("cvt.rna.tf32.f32 %0, %1;" : "=r"(r) : "f"(f));
    return r;
}
__device__ __forceinline__ float ex2(float x) {
    float r;
    asm("ex2.approx.ftz.f32 %0, %1;" : "=f"(r) : "f"(x));
    return r;
}
__device__ __forceinline__ uint32_t smem_u32(const void* p) {
    uint32_t a;
    asm("{ .reg .u64 t; cvta.to.shared.u64 t, %1; cvt.u32.u64 %0, t; }"
        : "=r"(a) : "l"(p));
    return a;
}
__device__ __forceinline__ void cp_async16(uint32_t saddr, const void* gptr) {
    asm volatile("cp.async.cg.shared.global [%0], [%1], 16;"
                 :: "r"(saddr), "l"(gptr) : "memory");
}
#define CP_COMMIT() asm volatile("cp.async.commit_group;" ::: "memory")
#define CP_WAIT(n)  asm volatile("cp.async.wait_group %0;" :: "n"(n) : "memory")

// D += A(16x8) * B(8x8), tf32 inputs, fp32 accum
__device__ __forceinline__ void mma16n8k8(float c[4], const uint32_t a[4],
                                          const uint32_t b[2]) {
    asm volatile(
        "mma.sync.aligned.m16n8k8.row.col.f32.tf32.tf32.f32 "
        "{%0,%1,%2,%3}, {%4,%5,%6,%7}, {%8,%9}, {%0,%1,%2,%3};"
        : "+f"(c[0]), "+f"(c[1]), "+f"(c[2]), "+f"(c[3])
        : "r"(a[0]), "r"(a[1]), "r"(a[2]), "r"(a[3]), "r"(b[0]), "r"(b[1]));
}

// ---------------------------------------------------------------------------
// Transpose: dst[c*R + r] = src[r*C + c]   (src: [R, C])
// ---------------------------------------------------------------------------
__global__ void transpose_k(const float* __restrict__ src, float* __restrict__ dst,
                            int R, int C)
{
    __shared__ float t[32][33];
    int bx = blockIdx.x * 32;
    int by = blockIdx.y * 32;
    #pragma unroll
    for (int i = 0; i < 32; i += 8)
        t[threadIdx.y + i][threadIdx.x] =
            src[(size_t)(by + threadIdx.y + i) * C + bx + threadIdx.x];
    __syncthreads();
    #pragma unroll
    for (int i = 0; i < 32; i += 8)
        dst[(size_t)(bx + threadIdx.y + i) * R + by + threadIdx.x] =
            t[threadIdx.x][threadIdx.y + i];
}

// ---------------------------------------------------------------------------
// tf32 mma.sync GEMM (KC=16, 2 CTAs/SM). Optional tf32-rounded output.
// ---------------------------------------------------------------------------
#define KC 16
#define SSTRIDE 20
#define TILE_F (128 * SSTRIDE)

extern __shared__ float g_smem[];

__global__ __launch_bounds__(256, 2) void gemm_mma(
    const float* __restrict__ A, const float* __restrict__ Bt,
    const float* __restrict__ bias, float* __restrict__ C,
    int Ncols, int K, int addBias, int cvtOut)
{
    float* As[2] = { g_smem,              g_smem + 2 * TILE_F };
    float* Bs[2] = { g_smem + TILE_F,     g_smem + 3 * TILE_F };

    const int tid  = threadIdx.x;
    const int lane = tid & 31;
    const int wid  = tid >> 5;
    const int gid  = lane >> 2;
    const int tig  = lane & 3;
    const int wr   = wid >> 2;
    const int wc   = wid & 3;
    const int bm = blockIdx.y * 128, bn = blockIdx.x * 128;

    const float* Ag = A  + (size_t)bm * K;
    const float* Bg = Bt + (size_t)bn * K;

    float acc[4][4][4];
    #pragma unroll
    for (int mt = 0; mt < 4; mt++)
        #pragma unroll
        for (int nt = 0; nt < 4; nt++)
            #pragma unroll
            for (int i = 0; i < 4; i++) acc[mt][nt][i] = 0.f;

    float4 pa[2], pb[2];
    const int nch = K / KC;

    #pragma unroll
    for (int i = 0; i < 2; i++) {
        int slot = tid + i * 256;
        int row  = slot >> 2;
        int q    = slot & 3;
        pa[i] = *(const float4*)(Ag + (size_t)row * K + q * 4);
        pb[i] = *(const float4*)(Bg + (size_t)row * K + q * 4);
    }
    #pragma unroll
    for (int i = 0; i < 2; i++) {
        int slot = tid + i * 256;
        int row  = slot >> 2;
        int q    = slot & 3;
        float* pA = As[0] + row * SSTRIDE + q * 4;
        float* pB = Bs[0] + row * SSTRIDE + q * 4;
        pA[0] = __uint_as_float(f2tf32(pa[i].x));
        pA[1] = __uint_as_float(f2tf32(pa[i].y));
        pA[2] = __uint_as_float(f2tf32(pa[i].z));
        pA[3] = __uint_as_float(f2tf32(pa[i].w));
        pB[0] = __uint_as_float(f2tf32(pb[i].x));
        pB[1] = __uint_as_float(f2tf32(pb[i].y));
        pB[2] = __uint_as_float(f2tf32(pb[i].z));
        pB[3] = __uint_as_float(f2tf32(pb[i].w));
    }
    __syncthreads();

    for (int c = 0; c < nch; c++) {
        const int buf = c & 1;
        if (c + 1 < nch) {
            const float* Agn = Ag + (c + 1) * KC;
            const float* Bgn = Bg + (c + 1) * KC;
            #pragma unroll
            for (int i = 0; i < 2; i++) {
                int slot = tid + i * 256;
                int row  = slot >> 2;
                int q    = slot & 3;
                pa[i] = *(const float4*)(Agn + (size_t)row * K + q * 4);
                pb[i] = *(const float4*)(Bgn + (size_t)row * K + q * 4);
            }
        }

        const uint32_t* Au = (const uint32_t*)As[buf];
        const uint32_t* Bu = (const uint32_t*)Bs[buf];
        #pragma unroll
        for (int ks = 0; ks < 2; ks++) {
            const int k0 = ks * 8;
            uint32_t af[4][4], bf[4][2];
            #pragma unroll
            for (int mt = 0; mt < 4; mt++) {
                int rb = wr * 64 + mt * 16;
                af[mt][0] = Au[(rb + gid)     * SSTRIDE + k0 + tig];
                af[mt][1] = Au[(rb + gid + 8) * SSTRIDE + k0 + tig];
                af[mt][2] = Au[(rb + gid)     * SSTRIDE + k0 + tig + 4];
                af[mt][3] = Au[(rb + gid + 8) * SSTRIDE + k0 + tig + 4];
            }
            #pragma unroll
            for (int nt = 0; nt < 4; nt++) {
                int cb = wc * 32 + nt * 8 + gid;
                bf[nt][0] = Bu[cb * SSTRIDE + k0 + tig];
                bf[nt][1] = Bu[cb * SSTRIDE + k0 + tig + 4];
            }
            #pragma unroll
            for (int mt = 0; mt < 4; mt++)
                #pragma unroll
                for (int nt = 0; nt < 4; nt++)
                    mma16n8k8(acc[mt][nt], af[mt], bf[nt]);
        }

        if (c + 1 < nch) {
            const int nb = (c + 1) & 1;
            #pragma unroll
            for (int i = 0; i < 2; i++) {
                int slot = tid + i * 256;
                int row  = slot >> 2;
                int q    = slot & 3;
                float* pA = As[nb] + row * SSTRIDE + q * 4;
                float* pB = Bs[nb] + row * SSTRIDE + q * 4;
                pA[0] = __uint_as_float(f2tf32(pa[i].x));
                pA[1] = __uint_as_float(f2tf32(pa[i].y));
                pA[2] = __uint_as_float(f2tf32(pa[i].z));
                pA[3] = __uint_as_float(f2tf32(pa[i].w));
                pB[0] = __uint_as_float(f2tf32(pb[i].x));
                pB[1] = __uint_as_float(f2tf32(pb[i].y));
                pB[2] = __uint_as_float(f2tf32(pb[i].z));
                pB[3] = __uint_as_float(f2tf32(pb[i].w));
            }
        }
        __syncthreads();
    }

    #pragma unroll
    for (int mt = 0; mt < 4; mt++) {
        int r0 = bm + wr * 64 + mt * 16 + gid;
        #pragma unroll
        for (int nt = 0; nt < 4; nt++) {
            int cc = bn + wc * 32 + nt * 8 + tig * 2;
            float b0 = 0.f, b1 = 0.f;
            if (addBias) { b0 = bias[cc]; b1 = bias[cc + 1]; }
            float2 v0 = { acc[mt][nt][0] + b0, acc[mt][nt][1] + b1 };
            float2 v1 = { acc[mt][nt][2] + b0, acc[mt][nt][3] + b1 };
            if (cvtOut) {
                v0.x = __uint_as_float(f2tf32(v0.x));
                v0.y = __uint_as_float(f2tf32(v0.y));
                v1.x = __uint_as_float(f2tf32(v1.x));
                v1.y = __uint_as_float(f2tf32(v1.y));
            }
            *(float2*)(C + (size_t)r0 * Ncols + cc)       = v0;
            *(float2*)(C + (size_t)(r0 + 8) * Ncols + cc) = v1;
        }
    }
}

// ---------------------------------------------------------------------------
// Tensor-core flash attention, v4:
//  - qkv is pre-rounded to tf32 by GEMM1 epilogue -> raw fragment loads,
//    NO conversion pass, NO per-fragment cvt
//  - cp.async double-buffered K/V, 2 CTAs/SM, exp2-domain softmax
// Smem: KV[2][128][72] + Ss[128][72] floats = 110592 B.
// ---------------------------------------------------------------------------
#define AST 72
#define KT  64
#define NTILES (SEQ / KT)

__global__ __launch_bounds__(256, 2) void attn_mma()
{
    float* KV[2] = { g_smem, g_smem + 128 * AST };      // K rows 0..63, V rows 64..127
    float* Ss    = g_smem + 2 * 128 * AST;              // [128][72]

    const int tid  = threadIdx.x;
    const int lane = tid & 31;
    const int wid  = tid >> 5;          // 0..7
    const int gid  = lane >> 2;         // 0..7
    const int tig  = lane & 3;          // 0..3
    const int wb   = wid * 16;

    const int bh = blockIdx.y;
    const int b  = bh / NHEAD;
    const int h  = bh - b * NHEAD;
    const int qbase = blockIdx.x * 128;

    const float* kbase = g_qkv + (size_t)(b * SEQ) * QKVC + DIM + h * HDIM;
    const float* vbase = kbase + DIM;

    const int srow = tid >> 4;           // 0..15
    const int sq   = tid & 15;
    uint32_t kv_s[2][2];
    #pragma unroll
    for (int bu = 0; bu < 2; bu++) {
        kv_s[bu][0] = smem_u32(KV[bu] + srow * AST + sq * 4);
        kv_s[bu][1] = smem_u32(KV[bu] + (64 + srow) * AST + sq * 4);
    }

    // ---- Q fragments (A operand), scaled by ATT_SCALE*log2e, tf32 ----
    uint32_t qf[8][4];
    {
        const float qs = ATT_SCALE * LOG2E;
        const float* Qg = g_qkv + (size_t)(b * SEQ + qbase + wb) * QKVC + h * HDIM;
        #pragma unroll
        for (int ks = 0; ks < 8; ks++) {
            int k0 = ks * 8;
            qf[ks][0] = f2tf32(Qg[(size_t)gid       * QKVC + k0 + tig]     * qs);
            qf[ks][1] = f2tf32(Qg[(size_t)(gid + 8) * QKVC + k0 + tig]     * qs);
            qf[ks][2] = f2tf32(Qg[(size_t)gid       * QKVC + k0 + tig + 4] * qs);
            qf[ks][3] = f2tf32(Qg[(size_t)(gid + 8) * QKVC + k0 + tig + 4] * qs);
        }
    }

    float of[8][4];
    #pragma unroll
    for (int nt = 0; nt < 8; nt++)
        #pragma unroll
        for (int i = 0; i < 4; i++) of[nt][i] = 0.f;
    float m0 = -1e30f, m1 = -1e30f, l0 = 0.f, l1 = 0.f;

    // ---- stage tile 0 ----
    #pragma unroll
    for (int i = 0; i < 4; i++) {
        int row = srow + i * 16;
        cp_async16(kv_s[0][0] + i * 16 * AST * 4,
                   kbase + (size_t)row * QKVC + sq * 4);
        cp_async16(kv_s[0][1] + i * 16 * AST * 4,
                   vbase + (size_t)row * QKVC + sq * 4);
    }
    CP_COMMIT();

    for (int t = 0; t < NTILES; t++) {
        const int buf = t & 1;
        if (t + 1 < NTILES) {
            const int nb = buf ^ 1;
            const int kt = (t + 1) * KT;
            #pragma unroll
            for (int i = 0; i < 4; i++) {
                int row = srow + i * 16;
                cp_async16(kv_s[nb][0] + i * 16 * AST * 4,
                           kbase + (size_t)(kt + row) * QKVC + sq * 4);
                cp_async16(kv_s[nb][1] + i * 16 * AST * 4,
                           vbase + (size_t)(kt + row) * QKVC + sq * 4);
            }
            CP_COMMIT();
            CP_WAIT(1);
        } else {
            CP_WAIT(0);
        }
        __syncthreads();

        const uint32_t* Ku = (const uint32_t*)KV[buf];
        const uint32_t* Vu = (const uint32_t*)(KV[buf] + 64 * AST);

        // ---- S = Q @ K^T (raw loads; data already tf32) ----
        float sc[8][4];
        #pragma unroll
        for (int nt = 0; nt < 8; nt++)
            #pragma unroll
            for (int i = 0; i < 4; i++) sc[nt][i] = 0.f;

        #pragma unroll
        for (int ks = 0; ks < 8; ks++) {
            const int k0 = ks * 8;
            #pragma unroll
            for (int nt = 0; nt < 8; nt++) {
                uint32_t bf[2];
                bf[0] = Ku[(nt * 8 + gid) * AST + k0 + tig];
                bf[1] = Ku[(nt * 8 + gid) * AST + k0 + tig + 4];
                mma16n8k8(sc[nt], qf[ks], bf);
            }
        }

        // ---- online softmax (log2 domain, quad shfl reductions) ----
        float tm0 = -1e30f, tm1 = -1e30f;
        #pragma unroll
        for (int nt = 0; nt < 8; nt++) {
            tm0 = fmaxf(tm0, fmaxf(sc[nt][0], sc[nt][1]));
            tm1 = fmaxf(tm1, fmaxf(sc[nt][2], sc[nt][3]));
        }
        tm0 = fmaxf(tm0, __shfl_xor_sync(0xffffffffu, tm0, 1));
        tm0 = fmaxf(tm0, __shfl_xor_sync(0xffffffffu, tm0, 2));
        tm1 = fmaxf(tm1, __shfl_xor_sync(0xffffffffu, tm1, 1));
        tm1 = fmaxf(tm1, __shfl_xor_sync(0xffffffffu, tm1, 2));

        float m0n = fmaxf(m0, tm0);
        float m1n = fmaxf(m1, tm1);
        float c0 = ex2(m0 - m0n);
        float c1 = ex2(m1 - m1n);

        float s0 = 0.f, s1 = 0.f;
        #pragma unroll
        for (int nt = 0; nt < 8; nt++) {
            sc[nt][0] = ex2(sc[nt][0] - m0n);
            sc[nt][1] = ex2(sc[nt][1] - m0n);
            sc[nt][2] = ex2(sc[nt][2] - m1n);
            sc[nt][3] = ex2(sc[nt][3] - m1n);
            s0 += sc[nt][0] + sc[nt][1];
            s1 += sc[nt][2] + sc[nt][3];
        }
        s0 += __shfl_xor_sync(0xffffffffu, s0, 1);
        s0 += __shfl_xor_sync(0xffffffffu, s0, 2);
        s1 += __shfl_xor_sync(0xffffffffu, s1, 1);
        s1 += __shfl_xor_sync(0xffffffffu, s1, 2);

        l0 = l0 * c0 + s0;
        l1 = l1 * c1 + s1;
        m0 = m0n; m1 = m1n;

        #pragma unroll
        for (int nt = 0; nt < 8; nt++) {
            of[nt][0] *= c0; of[nt][1] *= c0;
            of[nt][2] *= c1; of[nt][3] *= c1;
        }

        // ---- stage P (tf32) via smem (warp-private rows) ----
        #pragma unroll
        for (int nt = 0; nt < 8; nt++) {
            float2 p0 = { __uint_as_float(f2tf32(sc[nt][0])),
                          __uint_as_float(f2tf32(sc[nt][1])) };
            float2 p1 = { __uint_as_float(f2tf32(sc[nt][2])),
                          __uint_as_float(f2tf32(sc[nt][3])) };
            *(float2*)(Ss + (wb + gid)     * AST + nt * 8 + tig * 2) = p0;
            *(float2*)(Ss + (wb + gid + 8) * AST + nt * 8 + tig * 2) = p1;
        }
        __syncwarp();

        // ---- O += P @ V ----
        const uint32_t* Pu = (const uint32_t*)Ss;
        #pragma unroll
        for (int ks = 0; ks < 8; ks++) {
            const int k0 = ks * 8;
            uint32_t af[4];
            af[0] = Pu[(wb + gid)     * AST + k0 + tig];
            af[1] = Pu[(wb + gid + 8) * AST + k0 + tig];
            af[2] = Pu[(wb + gid)     * AST + k0 + tig + 4];
            af[3] = Pu[(wb + gid + 8) * AST + k0 + tig + 4];
            #pragma unroll
            for (int nt = 0; nt < 8; nt++) {
                uint32_t bf[2];
                bf[0] = Vu[(k0 + tig)     * AST + nt * 8 + gid];
                bf[1] = Vu[(k0 + tig + 4) * AST + nt * 8 + gid];
                mma16n8k8(of[nt], af, bf);
            }
        }
        __syncthreads();   // all warps done with buf before it is restaged
    }

    // ---- epilogue ----
    const float inv0 = 1.f / l0;
    const float inv1 = 1.f / l1;
    const int r0 = b * SEQ + qbase + wb + gid;
    #pragma unroll
    for (int nt = 0; nt < 8; nt++) {
        int col = h * HDIM + nt * 8 + tig * 2;
        float2 v0 = { of[nt][0] * inv0, of[nt][1] * inv0 };
        float2 v1 = { of[nt][2] * inv1, of[nt][3] * inv1 };
        *(float2*)(g_att + (size_t)r0 * DIM + col)       = v0;
        *(float2*)(g_att + (size_t)(r0 + 8) * DIM + col) = v1;
    }
}

// ---------------------------------------------------------------------------
extern "C" void kernel_launch(void* const* d_in, const int* in_sizes, int n_in,
                              void* d_out, int out_size)
{
    const float* x     = (const float*)d_in[0];   // [4,2048,768]
    const float* Wqkv  = (const float*)d_in[1];   // [768,2304]
    const float* Wproj = (const float*)d_in[2];   // [768,768]
    const float* bproj = (const float*)d_in[3];   // [768]
    float* out = (float*)d_out;

    float *qkv_ptr, *att_ptr, *wt1_ptr, *wt2_ptr;
    cudaGetSymbolAddress((void**)&qkv_ptr, g_qkv);
    cudaGetSymbolAddress((void**)&att_ptr, g_att);
    cudaGetSymbolAddress((void**)&wt1_ptr, g_Wt1);
    cudaGetSymbolAddress((void**)&wt2_ptr, g_Wt2);

    const int smem_gemm = 4 * TILE_F * sizeof(float);              // 40960
    const int smem_attn = (2 * 128 + 128) * AST * sizeof(float);   // 110592
    cudaFuncSetAttribute(gemm_mma, cudaFuncAttributeMaxDynamicSharedMemorySize,
                         smem_gemm);
    cudaFuncSetAttribute(attn_mma, cudaFuncAttributeMaxDynamicSharedMemorySize,
                         smem_attn);

    // 0) transpose weights to K-major
    transpose_k<<<dim3(QKVC / 32, DIM / 32), dim3(32, 8)>>>(Wqkv, wt1_ptr, DIM, QKVC);
    transpose_k<<<dim3(DIM / 32, DIM / 32), dim3(32, 8)>>>(Wproj, wt2_ptr, DIM, DIM);

    // 1) qkv = x @ Wqkv  (tf32 mma.sync; output pre-rounded to tf32)
    gemm_mma<<<dim3(QKVC / 128, ROWS / 128), 256, smem_gemm>>>(
        x, wt1_ptr, nullptr, qkv_ptr, QKVC, DIM, 0, 1);

    // 2) attention (tensor-core flash, raw tf32 fragments)
    attn_mma<<<dim3(SEQ / 128, BATCH * NHEAD), 256, smem_attn>>>();

    // 3) out = att @ Wproj + bproj (tf32 mma.sync, fp32 output)
    gemm_mma<<<dim3(DIM / 128, ROWS / 128), 256, smem_gemm>>>(
        att_ptr, wt2_ptr, bproj, out, DIM, DIM, 1, 0);
}

// round 8
// speedup vs baseline: 1.1418x; 1.0677x over previous
#include <cuda_runtime.h>
#include <cstdint>

#define BATCH 4
#define SEQ   2048
#define DIM   768
#define NHEAD 12
#define HDIM  64
#define QKVC  (3*DIM)            // 2304
#define ROWS  (BATCH*SEQ)        // 8192
#define ATT_SCALE 0.125f
#define LOG2E 1.44269504088896340736f

// Scratch (allocation-free rule: __device__ globals)
__device__ float g_qkv[(size_t)ROWS * QKVC];   // [B*N, 3*H*D] (tf32-rounded)
__device__ float g_att[(size_t)ROWS * DIM];    // [B*N, H*D]
__device__ float g_Wt1[(size_t)QKVC * DIM];    // Wqkv^T  [2304, 768] (K-major)
__device__ float g_Wt2[(size_t)DIM * DIM];     // Wproj^T [768, 768]

// ---------------------------------------------------------------------------
// helpers (non-'a' features only: supported on plain sm_103 target)
// ---------------------------------------------------------------------------
__device__ __forceinline__ uint32_t f2tf32(float f) {
    uint32_t r;
    asm("cvt.rna.tf32.f32 %0, %1;" : "=r"(r) : "f"(f));
    return r;
}
__device__ __forceinline__ float ex2(float x) {
    float r;
    asm("ex2.approx.ftz.f32 %0, %1;" : "=f"(r) : "f"(x));
    return r;
}
__device__ __forceinline__ uint32_t smem_u32(const void* p) {
    uint32_t a;
    asm("{ .reg .u64 t; cvta.to.shared.u64 t, %1; cvt.u32.u64 %0, t; }"
        : "=r"(a) : "l"(p));
    return a;
}
__device__ __forceinline__ void cp_async16(uint32_t saddr, const void* gptr) {
    asm volatile("cp.async.cg.shared.global [%0], [%1], 16;"
                 :: "r"(saddr), "l"(gptr) : "memory");
}
#define CP_COMMIT() asm volatile("cp.async.commit_group;" ::: "memory")
#define CP_WAIT(n)  asm volatile("cp.async.wait_group %0;" :: "n"(n) : "memory")

// D += A(16x8) * B(8x8), tf32 inputs, fp32 accum
__device__ __forceinline__ void mma16n8k8(float c[4], const uint32_t a[4],
                                          const uint32_t b[2]) {
    asm volatile(
        "mma.sync.aligned.m16n8k8.row.col.f32.tf32.tf32.f32 "
        "{%0,%1,%2,%3}, {%4,%5,%6,%7}, {%8,%9}, {%0,%1,%2,%3};"
        : "+f"(c[0]), "+f"(c[1]), "+f"(c[2]), "+f"(c[3])
        : "r"(a[0]), "r"(a[1]), "r"(a[2]), "r"(a[3]), "r"(b[0]), "r"(b[1]));
}

// ---------------------------------------------------------------------------
// Transpose: dst[c*R + r] = src[r*C + c]   (src: [R, C])
// ---------------------------------------------------------------------------
__global__ void transpose_k(const float* __restrict__ src, float* __restrict__ dst,
                            int R, int C)
{
    __shared__ float t[32][33];
    int bx = blockIdx.x * 32;
    int by = blockIdx.y * 32;
    #pragma unroll
    for (int i = 0; i < 32; i += 8)
        t[threadIdx.y + i][threadIdx.x] =
            src[(size_t)(by + threadIdx.y + i) * C + bx + threadIdx.x];
    __syncthreads();
    #pragma unroll
    for (int i = 0; i < 32; i += 8)
        dst[(size_t)(bx + threadIdx.y + i) * R + by + threadIdx.x] =
            t[threadIdx.x][threadIdx.y + i];
}

// ---------------------------------------------------------------------------
// tf32 mma.sync GEMM (KC=16, 2 CTAs/SM), paired LDS.64 fragment loads.
// k-mapping inside each k8-block: logical (tig, tig+4) -> physical (2tig, 2tig+1).
// Consistent for A and B, so the result is unchanged.
// ---------------------------------------------------------------------------
#define KC 16
#define SSTRIDE 20
#define TILE_F (128 * SSTRIDE)

extern __shared__ float g_smem[];

__global__ __launch_bounds__(256, 2) void gemm_mma(
    const float* __restrict__ A, const float* __restrict__ Bt,
    const float* __restrict__ bias, float* __restrict__ C,
    int Ncols, int K, int addBias, int cvtOut)
{
    float* As[2] = { g_smem,              g_smem + 2 * TILE_F };
    float* Bs[2] = { g_smem + TILE_F,     g_smem + 3 * TILE_F };

    const int tid  = threadIdx.x;
    const int lane = tid & 31;
    const int wid  = tid >> 5;
    const int gid  = lane >> 2;
    const int tig  = lane & 3;
    const int wr   = wid >> 2;
    const int wc   = wid & 3;
    const int bm = blockIdx.y * 128, bn = blockIdx.x * 128;

    const float* Ag = A  + (size_t)bm * K;
    const float* Bg = Bt + (size_t)bn * K;

    float acc[4][4][4];
    #pragma unroll
    for (int mt = 0; mt < 4; mt++)
        #pragma unroll
        for (int nt = 0; nt < 4; nt++)
            #pragma unroll
            for (int i = 0; i < 4; i++) acc[mt][nt][i] = 0.f;

    float4 pa[2], pb[2];
    const int nch = K / KC;

    #pragma unroll
    for (int i = 0; i < 2; i++) {
        int slot = tid + i * 256;
        int row  = slot >> 2;
        int q    = slot & 3;
        pa[i] = *(const float4*)(Ag + (size_t)row * K + q * 4);
        pb[i] = *(const float4*)(Bg + (size_t)row * K + q * 4);
    }
    #pragma unroll
    for (int i = 0; i < 2; i++) {
        int slot = tid + i * 256;
        int row  = slot >> 2;
        int q    = slot & 3;
        float* pA = As[0] + row * SSTRIDE + q * 4;
        float* pB = Bs[0] + row * SSTRIDE + q * 4;
        pA[0] = __uint_as_float(f2tf32(pa[i].x));
        pA[1] = __uint_as_float(f2tf32(pa[i].y));
        pA[2] = __uint_as_float(f2tf32(pa[i].z));
        pA[3] = __uint_as_float(f2tf32(pa[i].w));
        pB[0] = __uint_as_float(f2tf32(pb[i].x));
        pB[1] = __uint_as_float(f2tf32(pb[i].y));
        pB[2] = __uint_as_float(f2tf32(pb[i].z));
        pB[3] = __uint_as_float(f2tf32(pb[i].w));
    }
    __syncthreads();

    for (int c = 0; c < nch; c++) {
        const int buf = c & 1;
        if (c + 1 < nch) {
            const float* Agn = Ag + (c + 1) * KC;
            const float* Bgn = Bg + (c + 1) * KC;
            #pragma unroll
            for (int i = 0; i < 2; i++) {
                int slot = tid + i * 256;
                int row  = slot >> 2;
                int q    = slot & 3;
                pa[i] = *(const float4*)(Agn + (size_t)row * K + q * 4);
                pb[i] = *(const float4*)(Bgn + (size_t)row * K + q * 4);
            }
        }

        const uint32_t* Au = (const uint32_t*)As[buf];
        const uint32_t* Bu = (const uint32_t*)Bs[buf];
        #pragma unroll
        for (int ks = 0; ks < 2; ks++) {
            const int k0 = ks * 8 + 2 * tig;
            uint32_t af[4][4], bf[4][2];
            #pragma unroll
            for (int mt = 0; mt < 4; mt++) {
                int rb = wr * 64 + mt * 16;
                uint2 a0 = *(const uint2*)(Au + (rb + gid)     * SSTRIDE + k0);
                uint2 a1 = *(const uint2*)(Au + (rb + gid + 8) * SSTRIDE + k0);
                af[mt][0] = a0.x; af[mt][1] = a1.x;
                af[mt][2] = a0.y; af[mt][3] = a1.y;
            }
            #pragma unroll
            for (int nt = 0; nt < 4; nt++) {
                int cb = wc * 32 + nt * 8 + gid;
                uint2 bb = *(const uint2*)(Bu + cb * SSTRIDE + k0);
                bf[nt][0] = bb.x; bf[nt][1] = bb.y;
            }
            #pragma unroll
            for (int mt = 0; mt < 4; mt++)
                #pragma unroll
                for (int nt = 0; nt < 4; nt++)
                    mma16n8k8(acc[mt][nt], af[mt], bf[nt]);
        }

        if (c + 1 < nch) {
            const int nb = (c + 1) & 1;
            #pragma unroll
            for (int i = 0; i < 2; i++) {
                int slot = tid + i * 256;
                int row  = slot >> 2;
                int q    = slot & 3;
                float* pA = As[nb] + row * SSTRIDE + q * 4;
                float* pB = Bs[nb] + row * SSTRIDE + q * 4;
                pA[0] = __uint_as_float(f2tf32(pa[i].x));
                pA[1] = __uint_as_float(f2tf32(pa[i].y));
                pA[2] = __uint_as_float(f2tf32(pa[i].z));
                pA[3] = __uint_as_float(f2tf32(pa[i].w));
                pB[0] = __uint_as_float(f2tf32(pb[i].x));
                pB[1] = __uint_as_float(f2tf32(pb[i].y));
                pB[2] = __uint_as_float(f2tf32(pb[i].z));
                pB[3] = __uint_as_float(f2tf32(pb[i].w));
            }
        }
        __syncthreads();
    }

    #pragma unroll
    for (int mt = 0; mt < 4; mt++) {
        int r0 = bm + wr * 64 + mt * 16 + gid;
        #pragma unroll
        for (int nt = 0; nt < 4; nt++) {
            int cc = bn + wc * 32 + nt * 8 + tig * 2;
            float b0 = 0.f, b1 = 0.f;
            if (addBias) { b0 = bias[cc]; b1 = bias[cc + 1]; }
            float2 v0 = { acc[mt][nt][0] + b0, acc[mt][nt][1] + b1 };
            float2 v1 = { acc[mt][nt][2] + b0, acc[mt][nt][3] + b1 };
            if (cvtOut) {
                v0.x = __uint_as_float(f2tf32(v0.x));
                v0.y = __uint_as_float(f2tf32(v0.y));
                v1.x = __uint_as_float(f2tf32(v1.x));
                v1.y = __uint_as_float(f2tf32(v1.y));
            }
            *(float2*)(C + (size_t)r0 * Ncols + cc)       = v0;
            *(float2*)(C + (size_t)(r0 + 8) * Ncols + cc) = v1;
        }
    }
}

// ---------------------------------------------------------------------------
// Tensor-core flash attention, v5:
//  - paired k-mapping: S C-fragment IS the PV A-fragment (no P smem round
//    trip, no syncwarp), K fragment loads are LDS.64
//  - 3-stage cp.async KV pipeline (stage t+2 after tile-t barrier)
//  - qkv pre-rounded to tf32 by GEMM1; raw fragment loads
// Smem: KV[3][128][72] floats = 110592 B. 2 CTAs/SM.
// ---------------------------------------------------------------------------
#define AST 72
#define KT  64
#define NTILES (SEQ / KT)

__global__ __launch_bounds__(256, 2) void attn_mma()
{
    float* KV[3] = { g_smem, g_smem + 128 * AST, g_smem + 256 * AST };

    const int tid  = threadIdx.x;
    const int lane = tid & 31;
    const int wid  = tid >> 5;          // 0..7
    const int gid  = lane >> 2;         // 0..7
    const int tig  = lane & 3;          // 0..3
    const int wb   = wid * 16;

    const int bh = blockIdx.y;
    const int b  = bh / NHEAD;
    const int h  = bh - b * NHEAD;
    const int qbase = blockIdx.x * 128;

    const float* kbase = g_qkv + (size_t)(b * SEQ) * QKVC + DIM + h * HDIM;
    const float* vbase = kbase + DIM;

    const int srow = tid >> 4;           // 0..15
    const int sq   = tid & 15;
    uint32_t kv_s[3][2];
    #pragma unroll
    for (int bu = 0; bu < 3; bu++) {
        kv_s[bu][0] = smem_u32(KV[bu] + srow * AST + sq * 4);
        kv_s[bu][1] = smem_u32(KV[bu] + (64 + srow) * AST + sq * 4);
    }

    // ---- Q fragments, paired-column mapping, scaled, tf32 ----
    uint32_t qf[8][4];
    {
        const float qs = ATT_SCALE * LOG2E;
        const float* Qg = g_qkv + (size_t)(b * SEQ + qbase + wb) * QKVC + h * HDIM;
        #pragma unroll
        for (int ks = 0; ks < 8; ks++) {
            int k0 = ks * 8 + 2 * tig;
            qf[ks][0] = f2tf32(Qg[(size_t)gid       * QKVC + k0]     * qs);
            qf[ks][1] = f2tf32(Qg[(size_t)(gid + 8) * QKVC + k0]     * qs);
            qf[ks][2] = f2tf32(Qg[(size_t)gid       * QKVC + k0 + 1] * qs);
            qf[ks][3] = f2tf32(Qg[(size_t)(gid + 8) * QKVC + k0 + 1] * qs);
        }
    }

    float of[8][4];
    #pragma unroll
    for (int nt = 0; nt < 8; nt++)
        #pragma unroll
        for (int i = 0; i < 4; i++) of[nt][i] = 0.f;
    float m0 = -1e30f, m1 = -1e30f, l0 = 0.f, l1 = 0.f;

    // ---- prologue: stage tiles 0 and 1 ----
    #pragma unroll
    for (int i = 0; i < 4; i++) {
        int row = srow + i * 16;
        cp_async16(kv_s[0][0] + i * 16 * AST * 4, kbase + (size_t)row * QKVC + sq * 4);
        cp_async16(kv_s[0][1] + i * 16 * AST * 4, vbase + (size_t)row * QKVC + sq * 4);
    }
    CP_COMMIT();
    #pragma unroll
    for (int i = 0; i < 4; i++) {
        int row = srow + i * 16;
        cp_async16(kv_s[1][0] + i * 16 * AST * 4,
                   kbase + (size_t)(KT + row) * QKVC + sq * 4);
        cp_async16(kv_s[1][1] + i * 16 * AST * 4,
                   vbase + (size_t)(KT + row) * QKVC + sq * 4);
    }
    CP_COMMIT();

    for (int t = 0; t < NTILES; t++) {
        if (t + 1 < NTILES) { CP_WAIT(1); } else { CP_WAIT(0); }
        __syncthreads();

        if (t + 2 < NTILES) {
            const int nb = (t + 2) % 3;
            const int kt = (t + 2) * KT;
            #pragma unroll
            for (int i = 0; i < 4; i++) {
                int row = srow + i * 16;
                cp_async16(kv_s[nb][0] + i * 16 * AST * 4,
                           kbase + (size_t)(kt + row) * QKVC + sq * 4);
                cp_async16(kv_s[nb][1] + i * 16 * AST * 4,
                           vbase + (size_t)(kt + row) * QKVC + sq * 4);
            }
            CP_COMMIT();
        }

        const int buf = t % 3;
        const uint32_t* Ku = (const uint32_t*)KV[buf];
        const uint32_t* Vu = (const uint32_t*)(KV[buf] + 64 * AST);

        // ---- S = Q @ K^T (paired LDS.64 K fragments) ----
        float sc[8][4];
        #pragma unroll
        for (int nt = 0; nt < 8; nt++)
            #pragma unroll
            for (int i = 0; i < 4; i++) sc[nt][i] = 0.f;

        #pragma unroll
        for (int ks = 0; ks < 8; ks++) {
            const int k0 = ks * 8 + 2 * tig;
            #pragma unroll
            for (int nt = 0; nt < 8; nt++) {
                uint2 kk = *(const uint2*)(Ku + (nt * 8 + gid) * AST + k0);
                uint32_t bf[2] = { kk.x, kk.y };
                mma16n8k8(sc[nt], qf[ks], bf);
            }
        }

        // ---- online softmax (log2 domain, quad shfl reductions) ----
        float tm0 = -1e30f, tm1 = -1e30f;
        #pragma unroll
        for (int nt = 0; nt < 8; nt++) {
            tm0 = fmaxf(tm0, fmaxf(sc[nt][0], sc[nt][1]));
            tm1 = fmaxf(tm1, fmaxf(sc[nt][2], sc[nt][3]));
        }
        tm0 = fmaxf(tm0, __shfl_xor_sync(0xffffffffu, tm0, 1));
        tm0 = fmaxf(tm0, __shfl_xor_sync(0xffffffffu, tm0, 2));
        tm1 = fmaxf(tm1, __shfl_xor_sync(0xffffffffu, tm1, 1));
        tm1 = fmaxf(tm1, __shfl_xor_sync(0xffffffffu, tm1, 2));

        float m0n = fmaxf(m0, tm0);
        float m1n = fmaxf(m1, tm1);
        float c0 = ex2(m0 - m0n);
        float c1 = ex2(m1 - m1n);

        float s0 = 0.f, s1 = 0.f;
        #pragma unroll
        for (int nt = 0; nt < 8; nt++) {
            sc[nt][0] = ex2(sc[nt][0] - m0n);
            sc[nt][1] = ex2(sc[nt][1] - m0n);
            sc[nt][2] = ex2(sc[nt][2] - m1n);
            sc[nt][3] = ex2(sc[nt][3] - m1n);
            s0 += sc[nt][0] + sc[nt][1];
            s1 += sc[nt][2] + sc[nt][3];
        }
        s0 += __shfl_xor_sync(0xffffffffu, s0, 1);
        s0 += __shfl_xor_sync(0xffffffffu, s0, 2);
        s1 += __shfl_xor_sync(0xffffffffu, s1, 1);
        s1 += __shfl_xor_sync(0xffffffffu, s1, 2);

        l0 = l0 * c0 + s0;
        l1 = l1 * c1 + s1;
        m0 = m0n; m1 = m1n;

        #pragma unroll
        for (int nt = 0; nt < 8; nt++) {
            of[nt][0] *= c0; of[nt][1] *= c0;
            of[nt][2] *= c1; of[nt][3] *= c1;
        }

        // ---- O += P @ V : P's C-fragment IS the A-fragment (paired mapping)
        #pragma unroll
        for (int ks = 0; ks < 8; ks++) {
            const int k0 = ks * 8 + 2 * tig;      // physical key rows k0, k0+1
            uint32_t af[4];
            af[0] = f2tf32(sc[ks][0]);
            af[1] = f2tf32(sc[ks][2]);
            af[2] = f2tf32(sc[ks][1]);
            af[3] = f2tf32(sc[ks][3]);
            #pragma unroll
            for (int nt = 0; nt < 8; nt++) {
                uint32_t bf[2];
                bf[0] = Vu[(k0)     * AST + nt * 8 + gid];
                bf[1] = Vu[(k0 + 1) * AST + nt * 8 + gid];
                mma16n8k8(of[nt], af, bf);
            }
        }
    }

    // ---- epilogue ----
    const float inv0 = 1.f / l0;
    const float inv1 = 1.f / l1;
    const int r0 = b * SEQ + qbase + wb + gid;
    #pragma unroll
    for (int nt = 0; nt < 8; nt++) {
        int col = h * HDIM + nt * 8 + tig * 2;
        float2 v0 = { of[nt][0] * inv0, of[nt][1] * inv0 };
        float2 v1 = { of[nt][2] * inv1, of[nt][3] * inv1 };
        *(float2*)(g_att + (size_t)r0 * DIM + col)       = v0;
        *(float2*)(g_att + (size_t)(r0 + 8) * DIM + col) = v1;
    }
}

// ---------------------------------------------------------------------------
extern "C" void kernel_launch(void* const* d_in, const int* in_sizes, int n_in,
                              void* d_out, int out_size)
{
    const float* x     = (const float*)d_in[0];   // [4,2048,768]
    const float* Wqkv  = (const float*)d_in[1];   // [768,2304]
    const float* Wproj = (const float*)d_in[2];   // [768,768]
    const float* bproj = (const float*)d_in[3];   // [768]
    float* out = (float*)d_out;

    float *qkv_ptr, *att_ptr, *wt1_ptr, *wt2_ptr;
    cudaGetSymbolAddress((void**)&qkv_ptr, g_qkv);
    cudaGetSymbolAddress((void**)&att_ptr, g_att);
    cudaGetSymbolAddress((void**)&wt1_ptr, g_Wt1);
    cudaGetSymbolAddress((void**)&wt2_ptr, g_Wt2);

    const int smem_gemm = 4 * TILE_F * sizeof(float);          // 40960
    const int smem_attn = 3 * 128 * AST * sizeof(float);       // 110592
    cudaFuncSetAttribute(gemm_mma, cudaFuncAttributeMaxDynamicSharedMemorySize,
                         smem_gemm);
    cudaFuncSetAttribute(attn_mma, cudaFuncAttributeMaxDynamicSharedMemorySize,
                         smem_attn);

    // 0) transpose weights to K-major
    transpose_k<<<dim3(QKVC / 32, DIM / 32), dim3(32, 8)>>>(Wqkv, wt1_ptr, DIM, QKVC);
    transpose_k<<<dim3(DIM / 32, DIM / 32), dim3(32, 8)>>>(Wproj, wt2_ptr, DIM, DIM);

    // 1) qkv = x @ Wqkv  (tf32 mma.sync; output pre-rounded to tf32)
    gemm_mma<<<dim3(QKVC / 128, ROWS / 128), 256, smem_gemm>>>(
        x, wt1_ptr, nullptr, qkv_ptr, QKVC, DIM, 0, 1);

    // 2) attention (tensor-core flash, register P, 3-stage pipeline)
    attn_mma<<<dim3(SEQ / 128, BATCH * NHEAD), 256, smem_attn>>>();

    // 3) out = att @ Wproj + bproj (tf32 mma.sync, fp32 output)
    gemm_mma<<<dim3(DIM / 128, ROWS / 128), 256, smem_gemm>>>(
        att_ptr, wt2_ptr, bproj, out, DIM, DIM, 1, 0);
}